// round 2
// baseline (speedup 1.0000x reference)
#include <cuda_runtime.h>
#include <cstdint>

#define NMAX  100000
#define EMAX  1600000
#define BINSMAX (NMAX * 2)

// ---------------- scratch (device globals; no runtime allocation) ----------------
__device__ float d_S[(size_t)NMAX * 256];    // per-node, per-relation mean-aggregated features [N][2][128]
__device__ float d_H[(size_t)NMAX * 128];    // layer-1 hidden activations
__device__ int   d_cnt[BINSMAX];             // (dst,rel) histogram
__device__ int   d_off[BINSMAX + 1];         // CSR offsets
__device__ int   d_cur[BINSMAX];             // scatter cursors
__device__ int   d_csr[EMAX];                // src index per CSR slot
__device__ float d_W1[384 * 128];            // [W1_root; W1_rel0; W1_rel1]
__device__ float d_W2[384 * 64];             // [W2_root; W2_rel0; W2_rel1]
__device__ int   d_is64;                     // 1 if edge buffers are int64, 0 if int32

// ---------------- dtype probe: are edge indices int64 or int32? ----------------
// If data is genuinely int64 (values < N), the first 32 int64 reads are all in [0,N).
// If data is int32, an int64 read combines two random indices -> astronomically large.
__global__ void detect_dtype_kernel(const void* ei, int N) {
    const long long* p = (const long long*)ei;
    int ok = 1;
    for (int i = 0; i < 32; i++) {
        long long v = p[i];
        if (v < 0 || v >= (long long)N) { ok = 0; break; }
    }
    d_is64 = ok;
}

__device__ __forceinline__ int load_idx(const void* p, size_t i, int is64, int N) {
    long long v = is64 ? ((const long long*)p)[i] : (long long)((const int*)p)[i];
    if (v < 0) v = 0;
    if (v >= N) v = N - 1;
    return (int)v;
}

// ---------------- CSR build ----------------
__global__ void zero_cnt_kernel(int bins) {
    int i = blockIdx.x * blockDim.x + threadIdx.x;
    if (i < bins) d_cnt[i] = 0;
}

__global__ void hist_kernel(const void* __restrict__ ei,
                            const void* __restrict__ et, int E, int N) {
    int e = blockIdx.x * blockDim.x + threadIdx.x;
    if (e >= E) return;
    int is64 = d_is64;
    int dst = load_idx(ei, (size_t)E + e, is64, N);
    int rel = load_idx(et, e, is64, 2);
    atomicAdd(&d_cnt[dst * 2 + rel], 1);
}

// single-block exclusive scan over bins (16 elems/thread, 1024 threads)
__global__ void scan_kernel(int n) {
    const int T = 1024, PER = 16;
    __shared__ int warp_sums[32];
    __shared__ int s_carry;
    int tid = threadIdx.x;
    if (tid == 0) s_carry = 0;
    __syncthreads();
    int nIter = (n + T * PER - 1) / (T * PER);
    for (int it = 0; it < nIter; it++) {
        int i0 = it * T * PER + tid * PER;
        int vals[PER];
        int sum = 0;
#pragma unroll
        for (int p = 0; p < PER; p++) {
            int i = i0 + p;
            int v = (i < n) ? d_cnt[i] : 0;
            vals[p] = sum;
            sum += v;
        }
        int lane = tid & 31, wid = tid >> 5;
        int incl = sum;
#pragma unroll
        for (int d = 1; d < 32; d <<= 1) {
            int t = __shfl_up_sync(0xffffffffu, incl, d);
            if (lane >= d) incl += t;
        }
        if (lane == 31) warp_sums[wid] = incl;
        __syncthreads();
        if (wid == 0) {
            int w = warp_sums[lane];
#pragma unroll
            for (int d = 1; d < 32; d <<= 1) {
                int t = __shfl_up_sync(0xffffffffu, w, d);
                if (lane >= d) w += t;
            }
            warp_sums[lane] = w;
        }
        __syncthreads();
        int carry = s_carry;
        int warp_off = (wid > 0) ? warp_sums[wid - 1] : 0;
        int texcl = carry + warp_off + (incl - sum);
#pragma unroll
        for (int p = 0; p < PER; p++) {
            int i = i0 + p;
            if (i < n) {
                int o = texcl + vals[p];
                d_off[i] = o;
                d_cur[i] = o;
            }
        }
        int total = warp_sums[31];
        __syncthreads();
        if (tid == 0) s_carry = carry + total;
        __syncthreads();
    }
    if (tid == 0) d_off[n] = s_carry;
}

__global__ void scatter_kernel(const void* __restrict__ ei,
                               const void* __restrict__ et, int E, int N) {
    int e = blockIdx.x * blockDim.x + threadIdx.x;
    if (e >= E) return;
    int is64 = d_is64;
    int src = load_idx(ei, e, is64, N);
    int dst = load_idx(ei, (size_t)E + e, is64, N);
    int rel = load_idx(et, e, is64, 2);
    int pos = atomicAdd(&d_cur[dst * 2 + rel], 1);
    if (pos < EMAX) d_csr[pos] = src;
}

// ---------------- weight concat: Wcat[384][nc] = [root(128); rel0(128); rel1(128)] ----------------
__global__ void build_wcat_kernel(const float* __restrict__ root,
                                  const float* __restrict__ rel,
                                  float* __restrict__ W, int nc) {
    int i = blockIdx.x * blockDim.x + threadIdx.x;
    if (i >= 384 * nc) return;
    int r = i / nc;
    W[i] = (r < 128) ? root[i] : rel[i - 128 * nc];
}

// ---------------- per-(dst,rel) mean aggregation: one warp per segment ----------------
__global__ void aggregate_kernel(const float* __restrict__ feat, int bins) {
    int w = (blockIdx.x * blockDim.x + threadIdx.x) >> 5;
    int lane = threadIdx.x & 31;
    if (w >= bins) return;
    int beg = d_off[w], end = d_off[w + 1];
    float4 acc = make_float4(0.f, 0.f, 0.f, 0.f);
    int e = beg;
    for (; e + 2 <= end; e += 2) {
        int s0 = d_csr[e], s1 = d_csr[e + 1];
        float4 v0 = __ldg((const float4*)(feat + (size_t)s0 * 128) + lane);
        float4 v1 = __ldg((const float4*)(feat + (size_t)s1 * 128) + lane);
        acc.x += v0.x + v1.x;
        acc.y += v0.y + v1.y;
        acc.z += v0.z + v1.z;
        acc.w += v0.w + v1.w;
    }
    if (e < end) {
        int s0 = d_csr[e];
        float4 v0 = __ldg((const float4*)(feat + (size_t)s0 * 128) + lane);
        acc.x += v0.x;
        acc.y += v0.y;
        acc.z += v0.z;
        acc.w += v0.w;
    }
    int c = end - beg;
    float sc = 1.0f / (float)max(c, 1);
    acc.x *= sc; acc.y *= sc; acc.z *= sc; acc.w *= sc;
    ((float4*)(d_S + (size_t)w * 128))[lane] = acc;
}

// ---------------- fused GEMM: C[M,BN] = [A0 | A1] (M x 384) @ W (384 x BN) + bias, opt ReLU ----------------
// A0: ld 128 (k in [0,128)); A1: ld 256 (k in [128,384))
template <int BN, bool RELU>
__global__ void gemm_fused(const float* __restrict__ A0, const float* __restrict__ A1,
                           const float* __restrict__ W, const float* __restrict__ bias,
                           float* __restrict__ C, int M) {
    constexpr int BM = 128, BK = 16;
    constexpr int TX = BN / 8, TY = 16, T = TX * TY;
    __shared__ float As[BK][BM + 4];
    __shared__ float Bs[BK][BN];
    int tid = threadIdx.x;
    int tx = tid % TX, ty = tid / TX;
    int rowBase = blockIdx.x * BM;

    float acc[8][8];
#pragma unroll
    for (int i = 0; i < 8; i++)
#pragma unroll
        for (int j = 0; j < 8; j++) acc[i][j] = 0.f;

    for (int k0 = 0; k0 < 384; k0 += BK) {
        const float* Ab;
        int lda;
        if (k0 < 128) { Ab = A0 + k0; lda = 128; }
        else          { Ab = A1 + (k0 - 128); lda = 256; }
#pragma unroll
        for (int t = 0; t < (BM * BK / 4) / T; t++) {
            int idx = tid + t * T;
            int m = idx >> 2, q = idx & 3;
            int gm = rowBase + m;
            float4 v = make_float4(0.f, 0.f, 0.f, 0.f);
            if (gm < M) v = *(const float4*)(Ab + (size_t)gm * lda + q * 4);
            As[q * 4 + 0][m] = v.x;
            As[q * 4 + 1][m] = v.y;
            As[q * 4 + 2][m] = v.z;
            As[q * 4 + 3][m] = v.w;
        }
#pragma unroll
        for (int t = 0; t < (BK * BN / 4) / T; t++) {
            int idx = tid + t * T;
            int k = idx / (BN / 4), nq = idx % (BN / 4);
            float4 v = *(const float4*)(W + (size_t)(k0 + k) * BN + nq * 4);
            *(float4*)&Bs[k][nq * 4] = v;
        }
        __syncthreads();
#pragma unroll
        for (int kk = 0; kk < BK; kk++) {
            float a[8], b[8];
            *(float4*)&a[0] = *(const float4*)&As[kk][ty * 8];
            *(float4*)&a[4] = *(const float4*)&As[kk][ty * 8 + 4];
            *(float4*)&b[0] = *(const float4*)&Bs[kk][tx * 8];
            *(float4*)&b[4] = *(const float4*)&Bs[kk][tx * 8 + 4];
#pragma unroll
            for (int i = 0; i < 8; i++)
#pragma unroll
                for (int j = 0; j < 8; j++) acc[i][j] += a[i] * b[j];
        }
        __syncthreads();
    }

    float bv[8];
#pragma unroll
    for (int j = 0; j < 8; j++) bv[j] = bias[tx * 8 + j];
#pragma unroll
    for (int i = 0; i < 8; i++) {
        int row = rowBase + ty * 8 + i;
        if (row < M) {
#pragma unroll
            for (int jq = 0; jq < 2; jq++) {
                float4 o;
                o.x = acc[i][jq * 4 + 0] + bv[jq * 4 + 0];
                o.y = acc[i][jq * 4 + 1] + bv[jq * 4 + 1];
                o.z = acc[i][jq * 4 + 2] + bv[jq * 4 + 2];
                o.w = acc[i][jq * 4 + 3] + bv[jq * 4 + 3];
                if (RELU) {
                    o.x = fmaxf(o.x, 0.f); o.y = fmaxf(o.y, 0.f);
                    o.z = fmaxf(o.z, 0.f); o.w = fmaxf(o.w, 0.f);
                }
                *(float4*)&C[(size_t)row * BN + tx * 8 + jq * 4] = o;
            }
        }
    }
}

// ---------------- row-wise L2 normalize (in place), 64 cols ----------------
__global__ void l2norm_kernel(float* __restrict__ out, int M) {
    int r = blockIdx.x * blockDim.x + threadIdx.x;
    if (r >= M) return;
    float4* p = (float4*)(out + (size_t)r * 64);
    float4 v[16];
    float s = 0.f;
#pragma unroll
    for (int i = 0; i < 16; i++) {
        v[i] = p[i];
        s += v[i].x * v[i].x + v[i].y * v[i].y + v[i].z * v[i].z + v[i].w * v[i].w;
    }
    float nr = sqrtf(s);
    float sc = 1.0f / fmaxf(nr, 1e-12f);
#pragma unroll
    for (int i = 0; i < 16; i++) {
        v[i].x *= sc; v[i].y *= sc; v[i].z *= sc; v[i].w *= sc;
        p[i] = v[i];
    }
}

// ---------------- launch ----------------
extern "C" void kernel_launch(void* const* d_in, const int* in_sizes, int n_in,
                              void* d_out, int out_size) {
    const float* x       = (const float*)d_in[0];
    const void*  ei      = d_in[1];
    const void*  et      = d_in[2];
    const float* W1_rel  = (const float*)d_in[3];
    const float* W1_root = (const float*)d_in[4];
    const float* b1      = (const float*)d_in[5];
    const float* W2_rel  = (const float*)d_in[6];
    const float* W2_root = (const float*)d_in[7];
    const float* b2      = (const float*)d_in[8];
    float* out = (float*)d_out;

    int M = in_sizes[0] / 128;   // 100000 nodes
    int E = in_sizes[2];         // 1600000 edges (element count of edge_type)
    int bins = M * 2;

    float *S, *H, *W1c, *W2c;
    cudaGetSymbolAddress((void**)&S,   d_S);
    cudaGetSymbolAddress((void**)&H,   d_H);
    cudaGetSymbolAddress((void**)&W1c, d_W1);
    cudaGetSymbolAddress((void**)&W2c, d_W2);

    // probe edge-index dtype (int64 vs int32), then build CSR
    detect_dtype_kernel<<<1, 1>>>(ei, M);
    zero_cnt_kernel<<<(bins + 255) / 256, 256>>>(bins);
    hist_kernel<<<(E + 255) / 256, 256>>>(ei, et, E, M);
    scan_kernel<<<1, 1024>>>(bins);
    scatter_kernel<<<(E + 255) / 256, 256>>>(ei, et, E, M);

    // weight concatenation
    build_wcat_kernel<<<(384 * 128 + 255) / 256, 256>>>(W1_root, W1_rel, W1c, 128);
    build_wcat_kernel<<<(384 * 64 + 255) / 256, 256>>>(W2_root, W2_rel, W2c, 64);

    // layer 1: aggregate x -> S, then fused GEMM (+bias+ReLU) -> H
    aggregate_kernel<<<(bins * 32 + 255) / 256, 256>>>(x, bins);
    gemm_fused<128, true><<<(M + 127) / 128, 256>>>(x, S, W1c, b1, H, M);

    // layer 2: aggregate H -> S, fused GEMM (+bias) -> out
    aggregate_kernel<<<(bins * 32 + 255) / 256, 256>>>(H, bins);
    gemm_fused<64, false><<<(M + 127) / 128, 128>>>(H, S, W2c, b2, out, M);

    // final row-wise L2 normalize in place
    l2norm_kernel<<<(M + 255) / 256, 256>>>(out, M);
}